// round 6
// baseline (speedup 1.0000x reference)
#include <cuda_runtime.h>
#include <math.h>

#define NF   128   // num_filters
#define NG   50    // num_gauss
#define HID  128   // hidden
#define TE   64    // edges per tile
#define MAXN 50000
#define MAXE 800000

// Scratch (no allocation allowed)
__device__ float g_h[MAXN * NF];     // h = x @ lin1^T
__device__ float g_agg[MAXN * NF];   // segment_sum result
__device__ float g_tmp[MAXN * HID];  // ssp(agg @ lin2^T + b)
__device__ int   g_idx[2 * MAXE];    // normalized int32 edge indices [src | dst]
__device__ int   g_is64;             // dtype flag for edge_index

__device__ __forceinline__ float ssp(float v) {
    // softplus(v) - log(2), numerically stable
    return fmaxf(v, 0.0f) + log1pf(expf(-fabsf(v))) - 0.69314718055994531f;
}

// Swizzled index into a [K][128] transposed-weight smem tile.
// fg = filter-group (f/4). Reads: lanes have distinct fg -> conflict-free.
__device__ __forceinline__ int widx(int k, int fg) {
    return k * NF + (((fg) ^ (k & 31)) << 2);
}

// ---------------------------------------------------------------------------
// edge_index dtype detection + normalization to int32
// If int64 (values in [0, 50000)): every odd 32-bit word is zero.
// If int32: odd words are random node indices (all-zero prob ~ 0).
// ---------------------------------------------------------------------------
__global__ void detect_idx_kernel(const unsigned int* __restrict__ w, int nwords) {
    __shared__ int nonzero;
    if (threadIdx.x == 0) nonzero = 0;
    __syncthreads();
    int idx = 1 + 2 * (int)threadIdx.x;      // odd words 1,3,...,511
    if (idx < nwords && w[idx] != 0u) atomicExch(&nonzero, 1);
    __syncthreads();
    if (threadIdx.x == 0) g_is64 = (nonzero == 0) ? 1 : 0;
}

__global__ void convert_idx_kernel(const void* __restrict__ ei, int n2e) {
    int i = blockIdx.x * blockDim.x + threadIdx.x;
    if (i < n2e) {
        g_idx[i] = g_is64 ? (int)((const long long*)ei)[i]
                          : ((const int*)ei)[i];
    }
}

// ---------------------------------------------------------------------------
// zero kernel
// ---------------------------------------------------------------------------
__global__ void zero_kernel(float4* __restrict__ p, int n4) {
    int i = blockIdx.x * blockDim.x + threadIdx.x;
    if (i < n4) p[i] = make_float4(0.f, 0.f, 0.f, 0.f);
}

// ---------------------------------------------------------------------------
// Generic node GEMM: out[N,128] = op(A[N,128] @ W^T (+ bias)), W is [128][128]
// Tile: 64 rows x 128 cols per block, 256 threads, thread = 8 rows x 4 cols.
// ---------------------------------------------------------------------------
template <bool SSP, bool HASB>
__global__ void __launch_bounds__(256)
node_gemm(const float* __restrict__ A, const float* __restrict__ W,
          const float* __restrict__ bias, float* __restrict__ out, int N)
{
    extern __shared__ float sm[];
    float* wT = sm;            // 128*128 floats (swizzled, [k][f])
    float* aN = sm + NF * NF;  // 64*128 floats, row-major [r][k]

    const int tid = threadIdx.x;
    const int rbase = blockIdx.x * TE;

    // load W transposed+swizzled: W[f][k] -> wT[k][f]
    for (int i = tid; i < NF * NF; i += 256) {
        int f = i >> 7, k = i & (NF - 1);
        wT[widx(k, f >> 2) + (f & 3)] = W[i];
    }
    // load A tile (vectorized, coalesced)
    {
        const float4 z4 = make_float4(0.f, 0.f, 0.f, 0.f);
        for (int i = tid; i < TE * (NF / 4); i += 256) {
            int r = i >> 5;
            int gr = rbase + r;
            ((float4*)aN)[i] = (gr < N)
                ? ((const float4*)A)[(size_t)gr * (NF / 4) + (i & 31)] : z4;
        }
    }
    __syncthreads();

    const int fg = tid & 31, f0 = fg << 2;
    const int r0 = (tid >> 5) << 3;

    float acc[8][4];
#pragma unroll
    for (int i = 0; i < 8; i++)
#pragma unroll
        for (int j = 0; j < 4; j++) acc[i][j] = 0.f;

#pragma unroll 8
    for (int k = 0; k < NF; k++) {
        const float4 wv = *(const float4*)&wT[widx(k, fg)];
#pragma unroll
        for (int i = 0; i < 8; i++) {
            float a = aN[(r0 + i) * NF + k];   // warp-broadcast
            acc[i][0] = fmaf(a, wv.x, acc[i][0]);
            acc[i][1] = fmaf(a, wv.y, acc[i][1]);
            acc[i][2] = fmaf(a, wv.z, acc[i][2]);
            acc[i][3] = fmaf(a, wv.w, acc[i][3]);
        }
    }

    float4 bv = make_float4(0.f, 0.f, 0.f, 0.f);
    if (HASB) bv = *(const float4*)(bias + f0);

#pragma unroll
    for (int i = 0; i < 8; i++) {
        int gr = rbase + r0 + i;
        if (gr < N) {
            float4 v;
            v.x = acc[i][0] + bv.x;
            v.y = acc[i][1] + bv.y;
            v.z = acc[i][2] + bv.z;
            v.w = acc[i][3] + bv.w;
            if (SSP) { v.x = ssp(v.x); v.y = ssp(v.y); v.z = ssp(v.z); v.w = ssp(v.w); }
            *(float4*)(out + (size_t)gr * NF + f0) = v;
        }
    }
}

// ---------------------------------------------------------------------------
// Fused edge kernel: cutoff + 2-layer filter MLP + gather-mul + scatter-add.
// Persistent blocks (grid = #SMs); weights loaded to smem once per block.
// Per 64-edge tile: thread = 8 edges x 4 filters.
// ---------------------------------------------------------------------------
#define EDGE_SMEM_FLOATS (NF*NF + NG*NF + TE*NG + TE*NF + TE)
#define EDGE_SMEM_BYTES  (EDGE_SMEM_FLOATS * 4 + 2 * TE * 4)

__global__ void __launch_bounds__(256, 1)
edge_kernel(const float* __restrict__ ea, const float* __restrict__ ew,
            const float* __restrict__ w1, const float* __restrict__ b1,
            const float* __restrict__ w2, const float* __restrict__ b2,
            const float* __restrict__ h, float* __restrict__ agg, int E)
{
    extern __shared__ float sm[];
    float* w2T  = sm;                  // NF*NF  (swizzled [k][f])
    float* w1T  = w2T + NF * NF;       // NG*NF  (swizzled [k][f])
    float* eaR  = w1T + NG * NF;       // TE*NG  row-major [e][k]
    float* hN   = eaR + TE * NG;       // TE*NF  row-major [e][f]
    float* sC   = hN  + TE * NF;       // TE
    int*   sSrc = (int*)(sC + TE);     // TE
    int*   sDst = sSrc + TE;           // TE

    const int tid = threadIdx.x;

    // --- weights to smem once per (persistent) block ---
    for (int i = tid; i < NF * NF; i += 256) {
        int f = i >> 7, k = i & (NF - 1);
        w2T[widx(k, f >> 2) + (f & 3)] = w2[i];
    }
    for (int i = tid; i < NF * NG; i += 256) {
        int f = i / NG, k = i - f * NG;
        w1T[widx(k, f >> 2) + (f & 3)] = w1[i];
    }

    const int fg = tid & 31, f0 = fg << 2;
    const int e0 = (tid >> 5) << 3;
    const float4 b1v = *(const float4*)(b1 + f0);
    const float4 b2v = *(const float4*)(b2 + f0);

    const int ntiles = (E + TE - 1) / TE;
    for (int tile = blockIdx.x; tile < ntiles; tile += gridDim.x) {
        const int ebase = tile * TE;
        __syncthreads();  // protect smem reuse across iterations

        // --- load edge tile ---
        if (ebase + TE <= E) {
            const float4* eag = (const float4*)(ea + (size_t)ebase * NG);
            for (int i = tid; i < (TE * NG) / 4; i += 256)
                ((float4*)eaR)[i] = eag[i];
        } else {
            int valid = (E - ebase) * NG;
            for (int i = tid; i < TE * NG; i += 256)
                eaR[i] = (i < valid) ? ea[(size_t)ebase * NG + i] : 0.f;
        }
        if (tid < TE) {
            int ge = ebase + tid;
            if (ge < E) {
                sC[tid]   = 0.5f * (cospif(ew[ge] * 0.1f) + 1.0f);
                sSrc[tid] = g_idx[ge];
                sDst[tid] = g_idx[E + ge];
            } else {
                sC[tid] = 0.f; sSrc[tid] = 0; sDst[tid] = 0;
            }
        }
        __syncthreads();

        // --- prefetch h[src] gathers (L2-resident); hidden behind MLP FMAs ---
        float4 hs[8];
#pragma unroll
        for (int i = 0; i < 8; i++)
            hs[i] = *(const float4*)(h + (size_t)sSrc[e0 + i] * NF + f0);

        // --- layer 1: [TE,50] @ w1^T -> ssp -> hN[TE,128] ---
        float acc[8][4];
#pragma unroll
        for (int i = 0; i < 8; i++)
#pragma unroll
            for (int j = 0; j < 4; j++) acc[i][j] = 0.f;

#pragma unroll 10
        for (int k = 0; k < NG; k++) {
            const float4 wv = *(const float4*)&w1T[widx(k, fg)];
#pragma unroll
            for (int i = 0; i < 8; i++) {
                float a = eaR[(e0 + i) * NG + k];   // warp-broadcast
                acc[i][0] = fmaf(a, wv.x, acc[i][0]);
                acc[i][1] = fmaf(a, wv.y, acc[i][1]);
                acc[i][2] = fmaf(a, wv.z, acc[i][2]);
                acc[i][3] = fmaf(a, wv.w, acc[i][3]);
            }
        }
#pragma unroll
        for (int i = 0; i < 8; i++) {
            float4 v;
            v.x = ssp(acc[i][0] + b1v.x);
            v.y = ssp(acc[i][1] + b1v.y);
            v.z = ssp(acc[i][2] + b1v.z);
            v.w = ssp(acc[i][3] + b1v.w);
            *(float4*)&hN[(e0 + i) * NF + f0] = v;  // STS.128, conflict-free
        }
        __syncthreads();

        // --- layer 2: [TE,128] @ w2^T ---
        float acc2[8][4];
#pragma unroll
        for (int i = 0; i < 8; i++)
#pragma unroll
            for (int j = 0; j < 4; j++) acc2[i][j] = 0.f;

#pragma unroll 8
        for (int k = 0; k < NF; k++) {
            const float4 wv = *(const float4*)&w2T[widx(k, fg)];
#pragma unroll
            for (int i = 0; i < 8; i++) {
                float a = hN[(e0 + i) * NF + k];    // warp-broadcast
                acc2[i][0] = fmaf(a, wv.x, acc2[i][0]);
                acc2[i][1] = fmaf(a, wv.y, acc2[i][1]);
                acc2[i][2] = fmaf(a, wv.z, acc2[i][2]);
                acc2[i][3] = fmaf(a, wv.w, acc2[i][3]);
            }
        }

        // --- epilogue: W = (l2 + b2)*C, msg = h[src]*W, vector atomic scatter ---
#pragma unroll
        for (int i = 0; i < 8; i++) {
            int ge = ebase + e0 + i;
            if (ge < E) {
                float c = sC[e0 + i];
                int   d = sDst[e0 + i];
                float4 m;
                m.x = (acc2[i][0] + b2v.x) * c * hs[i].x;
                m.y = (acc2[i][1] + b2v.y) * c * hs[i].y;
                m.z = (acc2[i][2] + b2v.z) * c * hs[i].z;
                m.w = (acc2[i][3] + b2v.w) * c * hs[i].w;
                atomicAdd((float4*)(agg + (size_t)d * NF + f0), m);  // red.global.v4
            }
        }
    }
}

// ---------------------------------------------------------------------------
// launch
// ---------------------------------------------------------------------------
extern "C" void kernel_launch(void* const* d_in, const int* in_sizes, int n_in,
                              void* d_out, int out_size)
{
    const float* x      = (const float*)d_in[0];
    const void*  ei     = d_in[1];             // int32 or int64 — detected on device
    const float* ew     = (const float*)d_in[2];
    const float* ea     = (const float*)d_in[3];
    const float* mlp_w1 = (const float*)d_in[4];
    const float* mlp_b1 = (const float*)d_in[5];
    const float* mlp_w2 = (const float*)d_in[6];
    const float* mlp_b2 = (const float*)d_in[7];
    const float* lin1_w = (const float*)d_in[8];
    const float* lin2_w = (const float*)d_in[9];
    const float* lin2_b = (const float*)d_in[10];
    const float* lin_w  = (const float*)d_in[11];
    const float* lin_b  = (const float*)d_in[12];

    const int N = in_sizes[0] / HID;
    const int E = in_sizes[1] / 2;

    float *hbuf, *aggbuf, *tmpbuf;
    cudaGetSymbolAddress((void**)&hbuf,   g_h);
    cudaGetSymbolAddress((void**)&aggbuf, g_agg);
    cudaGetSymbolAddress((void**)&tmpbuf, g_tmp);

    const int NODE_SMEM = (NF * NF + TE * NF) * 4;   // 98304 B
    cudaFuncSetAttribute(edge_kernel, cudaFuncAttributeMaxDynamicSharedMemorySize, EDGE_SMEM_BYTES);
    cudaFuncSetAttribute(node_gemm<false, false>, cudaFuncAttributeMaxDynamicSharedMemorySize, NODE_SMEM);
    cudaFuncSetAttribute(node_gemm<true,  true >, cudaFuncAttributeMaxDynamicSharedMemorySize, NODE_SMEM);
    cudaFuncSetAttribute(node_gemm<false, true >, cudaFuncAttributeMaxDynamicSharedMemorySize, NODE_SMEM);

    int dev = 0;
    cudaGetDevice(&dev);
    int sms = 148;
    cudaDeviceGetAttribute(&sms, cudaDevAttrMultiProcessorCount, dev);

    // 0. normalize edge_index dtype -> int32 scratch
    //    (int32 array has 2E words; int64 has 4E words; we only inspect the
    //     first 513 words, safely within 2E words for either dtype)
    detect_idx_kernel<<<1, 256>>>((const unsigned int*)ei, 2 * E);
    convert_idx_kernel<<<(2 * E + 255) / 256, 256>>>(ei, 2 * E);

    // 1. zero agg
    {
        int n4 = (N * NF) / 4;
        zero_kernel<<<(n4 + 255) / 256, 256>>>((float4*)aggbuf, n4);
    }
    // 2. h = x @ lin1^T
    node_gemm<false, false><<<(N + TE - 1) / TE, 256, NODE_SMEM>>>(x, lin1_w, nullptr, hbuf, N);
    // 3. fused edge MLP + gather + scatter (persistent)
    edge_kernel<<<sms, 256, EDGE_SMEM_BYTES>>>(ea, ew, mlp_w1, mlp_b1,
                                               mlp_w2, mlp_b2, hbuf, aggbuf, E);
    // 4. tmp = ssp(agg @ lin2^T + b2)
    node_gemm<true, true><<<(N + TE - 1) / TE, 256, NODE_SMEM>>>(aggbuf, lin2_w, lin2_b, tmpbuf, N);
    // 5. out = tmp @ lin^T + b
    node_gemm<false, true><<<(N + TE - 1) / TE, 256, NODE_SMEM>>>(tmpbuf, lin_w, lin_b, (float*)d_out, N);
}

// round 7
// speedup vs baseline: 1.0675x; 1.0675x over previous
#include <cuda_runtime.h>
#include <math.h>

#define NF   128   // num_filters
#define NG   50    // num_gauss
#define HID  128   // hidden
#define TE   64    // edges per tile
#define MAXN 50000
#define MAXE 800000

typedef unsigned long long u64;

// Scratch (no allocation allowed)
__device__ float g_h[MAXN * NF];     // h = x @ lin1^T
__device__ float g_agg[MAXN * NF];   // segment_sum result
__device__ float g_tmp[MAXN * HID];  // ssp(agg @ lin2^T + b)
__device__ int   g_idx[2 * MAXE];    // normalized int32 edge indices [src | dst]
__device__ int   g_is64;             // dtype flag for edge_index

__device__ __forceinline__ float ssp(float v) {
    // softplus(v) - log(2), numerically stable
    return fmaxf(v, 0.0f) + log1pf(expf(-fabsf(v))) - 0.69314718055994531f;
}

// ---- packed fp32x2 helpers (Blackwell FFMA2) --------------------------------
__device__ __forceinline__ u64 splat2(float a) {
    u64 r; asm("mov.b64 %0, {%1, %1};" : "=l"(r) : "f"(a)); return r;
}
__device__ __forceinline__ void fma2(u64& d, u64 a, u64 b) {
    asm("fma.rn.f32x2 %0, %1, %2, %0;" : "+l"(d) : "l"(a), "l"(b));
}
__device__ __forceinline__ float2 unpack2(u64 v) {
    float2 f; asm("mov.b64 {%0, %1}, %2;" : "=f"(f.x), "=f"(f.y) : "l"(v)); return f;
}

// Swizzled index into a [K][128] transposed-weight smem tile.
// fg = filter-group (f/4). Reads: lanes have distinct fg -> conflict-free.
__device__ __forceinline__ int widx(int k, int fg) {
    return k * NF + (((fg) ^ (k & 31)) << 2);
}

// ---------------------------------------------------------------------------
// edge_index dtype detection + normalization to int32
// ---------------------------------------------------------------------------
__global__ void detect_idx_kernel(const unsigned int* __restrict__ w, int nwords) {
    __shared__ int nonzero;
    if (threadIdx.x == 0) nonzero = 0;
    __syncthreads();
    int idx = 1 + 2 * (int)threadIdx.x;      // odd words 1,3,...,511
    if (idx < nwords && w[idx] != 0u) atomicExch(&nonzero, 1);
    __syncthreads();
    if (threadIdx.x == 0) g_is64 = (nonzero == 0) ? 1 : 0;
}

__global__ void convert_idx_kernel(const void* __restrict__ ei, int n2e) {
    int i = blockIdx.x * blockDim.x + threadIdx.x;
    if (i < n2e) {
        g_idx[i] = g_is64 ? (int)((const long long*)ei)[i]
                          : ((const int*)ei)[i];
    }
}

// ---------------------------------------------------------------------------
// zero kernel
// ---------------------------------------------------------------------------
__global__ void zero_kernel(float4* __restrict__ p, int n4) {
    int i = blockIdx.x * blockDim.x + threadIdx.x;
    if (i < n4) p[i] = make_float4(0.f, 0.f, 0.f, 0.f);
}

// ---------------------------------------------------------------------------
// Generic node GEMM: out[N,128] = op(A[N,128] @ W^T (+ bias)), W is [128][128]
// Tile: 64 rows x 128 cols per block, 256 threads, thread = 8 rows x 4 cols.
// Inner loop in packed fp32x2 (FFMA2): 2 FMAs/instruction.
// ---------------------------------------------------------------------------
template <bool SSP, bool HASB>
__global__ void __launch_bounds__(256)
node_gemm(const float* __restrict__ A, const float* __restrict__ W,
          const float* __restrict__ bias, float* __restrict__ out, int N)
{
    extern __shared__ float sm[];
    float* wT = sm;            // 128*128 floats (swizzled, [k][f])
    float* aN = sm + NF * NF;  // 64*128 floats, row-major [r][k]

    const int tid = threadIdx.x;
    const int rbase = blockIdx.x * TE;

    for (int i = tid; i < NF * NF; i += 256) {
        int f = i >> 7, k = i & (NF - 1);
        wT[widx(k, f >> 2) + (f & 3)] = W[i];
    }
    {
        const float4 z4 = make_float4(0.f, 0.f, 0.f, 0.f);
        for (int i = tid; i < TE * (NF / 4); i += 256) {
            int r = i >> 5;
            int gr = rbase + r;
            ((float4*)aN)[i] = (gr < N)
                ? ((const float4*)A)[(size_t)gr * (NF / 4) + (i & 31)] : z4;
        }
    }
    __syncthreads();

    const int fg = tid & 31, f0 = fg << 2;
    const int r0 = (tid >> 5) << 3;

    u64 acc[8][2];
#pragma unroll
    for (int i = 0; i < 8; i++) { acc[i][0] = 0ULL; acc[i][1] = 0ULL; }

#pragma unroll 8
    for (int k = 0; k < NF; k++) {
        const ulonglong2 wv = *(const ulonglong2*)&wT[widx(k, fg)];  // LDS.128 -> 2x f32x2
#pragma unroll
        for (int i = 0; i < 8; i++) {
            u64 aa = splat2(aN[(r0 + i) * NF + k]);   // warp-broadcast LDS + ALU splat
            fma2(acc[i][0], aa, wv.x);
            fma2(acc[i][1], aa, wv.y);
        }
    }

    float4 bv = make_float4(0.f, 0.f, 0.f, 0.f);
    if (HASB) bv = *(const float4*)(bias + f0);

#pragma unroll
    for (int i = 0; i < 8; i++) {
        int gr = rbase + r0 + i;
        if (gr < N) {
            float2 p0 = unpack2(acc[i][0]);
            float2 p1 = unpack2(acc[i][1]);
            float4 v;
            v.x = p0.x + bv.x;
            v.y = p0.y + bv.y;
            v.z = p1.x + bv.z;
            v.w = p1.y + bv.w;
            if (SSP) { v.x = ssp(v.x); v.y = ssp(v.y); v.z = ssp(v.z); v.w = ssp(v.w); }
            *(float4*)(out + (size_t)gr * NF + f0) = v;
        }
    }
}

// ---------------------------------------------------------------------------
// Fused edge kernel: cutoff + 2-layer filter MLP + gather-mul + scatter-add.
// Persistent blocks (grid = #SMs); weights loaded to smem once per block.
// Per 64-edge tile: thread = 8 edges x 4 filters; FFMA2 inner loops.
// ---------------------------------------------------------------------------
#define EDGE_SMEM_FLOATS (NF*NF + NG*NF + TE*NG + TE*NF + TE)
#define EDGE_SMEM_BYTES  (EDGE_SMEM_FLOATS * 4 + 2 * TE * 4)

__global__ void __launch_bounds__(256, 1)
edge_kernel(const float* __restrict__ ea, const float* __restrict__ ew,
            const float* __restrict__ w1, const float* __restrict__ b1,
            const float* __restrict__ w2, const float* __restrict__ b2,
            const float* __restrict__ h, float* __restrict__ agg, int E)
{
    extern __shared__ float sm[];
    float* w2T  = sm;                  // NF*NF  (swizzled [k][f])
    float* w1T  = w2T + NF * NF;       // NG*NF  (swizzled [k][f])
    float* eaR  = w1T + NG * NF;       // TE*NG  row-major [e][k]
    float* hN   = eaR + TE * NG;       // TE*NF  row-major [e][f]
    float* sC   = hN  + TE * NF;       // TE
    int*   sSrc = (int*)(sC + TE);     // TE
    int*   sDst = sSrc + TE;           // TE

    const int tid = threadIdx.x;

    // --- weights to smem once per (persistent) block ---
    for (int i = tid; i < NF * NF; i += 256) {
        int f = i >> 7, k = i & (NF - 1);
        w2T[widx(k, f >> 2) + (f & 3)] = w2[i];
    }
    for (int i = tid; i < NF * NG; i += 256) {
        int f = i / NG, k = i - f * NG;
        w1T[widx(k, f >> 2) + (f & 3)] = w1[i];
    }

    const int fg = tid & 31, f0 = fg << 2;
    const int e0 = (tid >> 5) << 3;
    const float4 b1v = *(const float4*)(b1 + f0);
    const float4 b2v = *(const float4*)(b2 + f0);

    const int ntiles = (E + TE - 1) / TE;
    for (int tile = blockIdx.x; tile < ntiles; tile += gridDim.x) {
        const int ebase = tile * TE;
        __syncthreads();  // protect smem reuse across iterations

        // --- load edge tile ---
        if (ebase + TE <= E) {
            const float4* eag = (const float4*)(ea + (size_t)ebase * NG);
            for (int i = tid; i < (TE * NG) / 4; i += 256)
                ((float4*)eaR)[i] = eag[i];
        } else {
            int valid = (E - ebase) * NG;
            for (int i = tid; i < TE * NG; i += 256)
                eaR[i] = (i < valid) ? ea[(size_t)ebase * NG + i] : 0.f;
        }
        if (tid < TE) {
            int ge = ebase + tid;
            if (ge < E) {
                sC[tid]   = 0.5f * (cospif(ew[ge] * 0.1f) + 1.0f);
                sSrc[tid] = g_idx[ge];
                sDst[tid] = g_idx[E + ge];
            } else {
                sC[tid] = 0.f; sSrc[tid] = 0; sDst[tid] = 0;
            }
        }
        __syncthreads();

        // --- prefetch h[src] gathers (L2-resident); hidden behind MLP FMAs ---
        float4 hs[8];
#pragma unroll
        for (int i = 0; i < 8; i++)
            hs[i] = *(const float4*)(h + (size_t)sSrc[e0 + i] * NF + f0);

        // --- layer 1: [TE,50] @ w1^T -> ssp -> hN[TE,128] ---
        u64 acc[8][2];
#pragma unroll
        for (int i = 0; i < 8; i++) { acc[i][0] = 0ULL; acc[i][1] = 0ULL; }

#pragma unroll 10
        for (int k = 0; k < NG; k++) {
            const ulonglong2 wv = *(const ulonglong2*)&w1T[widx(k, fg)];
#pragma unroll
            for (int i = 0; i < 8; i++) {
                u64 aa = splat2(eaR[(e0 + i) * NG + k]);   // warp-broadcast
                fma2(acc[i][0], aa, wv.x);
                fma2(acc[i][1], aa, wv.y);
            }
        }
#pragma unroll
        for (int i = 0; i < 8; i++) {
            float2 p0 = unpack2(acc[i][0]);
            float2 p1 = unpack2(acc[i][1]);
            float4 v;
            v.x = ssp(p0.x + b1v.x);
            v.y = ssp(p0.y + b1v.y);
            v.z = ssp(p1.x + b1v.z);
            v.w = ssp(p1.y + b1v.w);
            *(float4*)&hN[(e0 + i) * NF + f0] = v;  // STS.128, conflict-free
        }
        __syncthreads();

        // --- layer 2: [TE,128] @ w2^T ---
        u64 acc2[8][2];
#pragma unroll
        for (int i = 0; i < 8; i++) { acc2[i][0] = 0ULL; acc2[i][1] = 0ULL; }

#pragma unroll 8
        for (int k = 0; k < NF; k++) {
            const ulonglong2 wv = *(const ulonglong2*)&w2T[widx(k, fg)];
#pragma unroll
            for (int i = 0; i < 8; i++) {
                u64 aa = splat2(hN[(e0 + i) * NF + k]);    // warp-broadcast
                fma2(acc2[i][0], aa, wv.x);
                fma2(acc2[i][1], aa, wv.y);
            }
        }

        // --- epilogue: W = (l2 + b2)*C, msg = h[src]*W, vector atomic scatter ---
#pragma unroll
        for (int i = 0; i < 8; i++) {
            int ge = ebase + e0 + i;
            if (ge < E) {
                float c = sC[e0 + i];
                int   d = sDst[e0 + i];
                float2 p0 = unpack2(acc2[i][0]);
                float2 p1 = unpack2(acc2[i][1]);
                float4 m;
                m.x = (p0.x + b2v.x) * c * hs[i].x;
                m.y = (p0.y + b2v.y) * c * hs[i].y;
                m.z = (p1.x + b2v.z) * c * hs[i].z;
                m.w = (p1.y + b2v.w) * c * hs[i].w;
                atomicAdd((float4*)(agg + (size_t)d * NF + f0), m);  // red.global.v4
            }
        }
    }
}

// ---------------------------------------------------------------------------
// launch
// ---------------------------------------------------------------------------
extern "C" void kernel_launch(void* const* d_in, const int* in_sizes, int n_in,
                              void* d_out, int out_size)
{
    const float* x      = (const float*)d_in[0];
    const void*  ei     = d_in[1];             // int32 or int64 — detected on device
    const float* ew     = (const float*)d_in[2];
    const float* ea     = (const float*)d_in[3];
    const float* mlp_w1 = (const float*)d_in[4];
    const float* mlp_b1 = (const float*)d_in[5];
    const float* mlp_w2 = (const float*)d_in[6];
    const float* mlp_b2 = (const float*)d_in[7];
    const float* lin1_w = (const float*)d_in[8];
    const float* lin2_w = (const float*)d_in[9];
    const float* lin2_b = (const float*)d_in[10];
    const float* lin_w  = (const float*)d_in[11];
    const float* lin_b  = (const float*)d_in[12];

    const int N = in_sizes[0] / HID;
    const int E = in_sizes[1] / 2;

    float *hbuf, *aggbuf, *tmpbuf;
    cudaGetSymbolAddress((void**)&hbuf,   g_h);
    cudaGetSymbolAddress((void**)&aggbuf, g_agg);
    cudaGetSymbolAddress((void**)&tmpbuf, g_tmp);

    const int NODE_SMEM = (NF * NF + TE * NF) * 4;   // 98304 B
    cudaFuncSetAttribute(edge_kernel, cudaFuncAttributeMaxDynamicSharedMemorySize, EDGE_SMEM_BYTES);
    cudaFuncSetAttribute(node_gemm<false, false>, cudaFuncAttributeMaxDynamicSharedMemorySize, NODE_SMEM);
    cudaFuncSetAttribute(node_gemm<true,  true >, cudaFuncAttributeMaxDynamicSharedMemorySize, NODE_SMEM);
    cudaFuncSetAttribute(node_gemm<false, true >, cudaFuncAttributeMaxDynamicSharedMemorySize, NODE_SMEM);

    int dev = 0;
    cudaGetDevice(&dev);
    int sms = 148;
    cudaDeviceGetAttribute(&sms, cudaDevAttrMultiProcessorCount, dev);

    // 0. normalize edge_index dtype -> int32 scratch
    detect_idx_kernel<<<1, 256>>>((const unsigned int*)ei, 2 * E);
    convert_idx_kernel<<<(2 * E + 255) / 256, 256>>>(ei, 2 * E);

    // 1. zero agg
    {
        int n4 = (N * NF) / 4;
        zero_kernel<<<(n4 + 255) / 256, 256>>>((float4*)aggbuf, n4);
    }
    // 2. h = x @ lin1^T
    node_gemm<false, false><<<(N + TE - 1) / TE, 256, NODE_SMEM>>>(x, lin1_w, nullptr, hbuf, N);
    // 3. fused edge MLP + gather + scatter (persistent)
    edge_kernel<<<sms, 256, EDGE_SMEM_BYTES>>>(ea, ew, mlp_w1, mlp_b1,
                                               mlp_w2, mlp_b2, hbuf, aggbuf, E);
    // 4. tmp = ssp(agg @ lin2^T + b2)
    node_gemm<true, true><<<(N + TE - 1) / TE, 256, NODE_SMEM>>>(aggbuf, lin2_w, lin2_b, tmpbuf, N);
    // 5. out = tmp @ lin^T + b
    node_gemm<false, true><<<(N + TE - 1) / TE, 256, NODE_SMEM>>>(tmpbuf, lin_w, lin_b, (float*)d_out, N);
}

// round 9
// speedup vs baseline: 1.1558x; 1.0826x over previous
#include <cuda_runtime.h>
#include <math.h>

#define NF   128   // num_filters
#define NG   50    // num_gauss
#define HID  128   // hidden
#define TE   64    // edges per tile
#define MAXN 50000
#define MAXE 800000

typedef unsigned long long u64;

// Scratch (no allocation allowed)
__device__ float g_h[MAXN * NF];     // h = x @ lin1^T
__device__ float g_agg[MAXN * NF];   // segment_sum result
__device__ float g_tmp[MAXN * HID];  // ssp(agg @ lin2^T + b)
__device__ float g_w1T[NG * NF];     // w1 transposed [k][f]
__device__ int   g_idx[2 * MAXE];    // normalized int32 edge indices [src | dst]
__device__ int   g_is64;             // dtype flag for edge_index

__device__ __forceinline__ float ssp(float v) {
    // softplus(v) - log(2), numerically stable
    return fmaxf(v, 0.0f) + log1pf(expf(-fabsf(v))) - 0.69314718055994531f;
}

// ---- packed fp32x2 helpers (Blackwell FFMA2) --------------------------------
__device__ __forceinline__ u64 splat2(float a) {
    u64 r; asm("mov.b64 %0, {%1, %1};" : "=l"(r) : "f"(a)); return r;
}
__device__ __forceinline__ void fma2(u64& d, u64 a, u64 b) {
    asm("fma.rn.f32x2 %0, %1, %2, %0;" : "+l"(d) : "l"(a), "l"(b));
}
__device__ __forceinline__ float2 unpack2(u64 v) {
    float2 f; asm("mov.b64 {%0, %1}, %2;" : "=f"(f.x), "=f"(f.y) : "l"(v)); return f;
}

// Swizzled index into a [K][128] transposed-weight smem tile.
// fg = filter-group (f/4). Reads: lanes have distinct fg -> conflict-free.
__device__ __forceinline__ int widx(int k, int fg) {
    return k * NF + (((fg) ^ (k & 31)) << 2);
}

// ---------------------------------------------------------------------------
// prep kernels
// ---------------------------------------------------------------------------
__global__ void detect_idx_kernel(const unsigned int* __restrict__ w, int nwords) {
    __shared__ int nonzero;
    if (threadIdx.x == 0) nonzero = 0;
    __syncthreads();
    int idx = 1 + 2 * (int)threadIdx.x;      // odd words 1,3,...,511
    if (idx < nwords && w[idx] != 0u) atomicExch(&nonzero, 1);
    __syncthreads();
    if (threadIdx.x == 0) g_is64 = (nonzero == 0) ? 1 : 0;
}

__global__ void convert_idx_kernel(const void* __restrict__ ei, int n2e) {
    int i = blockIdx.x * blockDim.x + threadIdx.x;
    if (i < n2e) {
        g_idx[i] = g_is64 ? (int)((const long long*)ei)[i]
                          : ((const int*)ei)[i];
    }
}

__global__ void transpose_w1_kernel(const float* __restrict__ w1) {
    // w1: [NF][NG] -> g_w1T: [NG][NF]
    int i = blockIdx.x * blockDim.x + threadIdx.x;
    if (i < NF * NG) {
        int f = i / NG, k = i - f * NG;
        g_w1T[k * NF + f] = w1[i];
    }
}

__global__ void zero_kernel(float4* __restrict__ p, int n4) {
    int i = blockIdx.x * blockDim.x + threadIdx.x;
    if (i < n4) p[i] = make_float4(0.f, 0.f, 0.f, 0.f);
}

// ---------------------------------------------------------------------------
// Generic node GEMM: out[N,128] = op(A[N,128] @ W^T (+ bias)), W is [128][128]
// Tile: 64 rows x 128 cols per block, 256 threads, thread = 8 rows x 4 cols.
// Inner loop in packed fp32x2 (FFMA2). smem 98 KB -> 2 blocks/SM.
// ---------------------------------------------------------------------------
template <bool SSP, bool HASB>
__global__ void __launch_bounds__(256)
node_gemm(const float* __restrict__ A, const float* __restrict__ W,
          const float* __restrict__ bias, float* __restrict__ out, int N)
{
    extern __shared__ float sm[];
    float* wT = sm;            // 128*128 floats (swizzled, [k][f])
    float* aN = sm + NF * NF;  // 64*128 floats, row-major [r][k]

    const int tid = threadIdx.x;
    const int rbase = blockIdx.x * TE;

    for (int i = tid; i < NF * NF; i += 256) {
        int f = i >> 7, k = i & (NF - 1);
        wT[widx(k, f >> 2) + (f & 3)] = W[i];
    }
    {
        const float4 z4 = make_float4(0.f, 0.f, 0.f, 0.f);
        for (int i = tid; i < TE * (NF / 4); i += 256) {
            int r = i >> 5;
            int gr = rbase + r;
            ((float4*)aN)[i] = (gr < N)
                ? ((const float4*)A)[(size_t)gr * (NF / 4) + (i & 31)] : z4;
        }
    }
    __syncthreads();

    const int fg = tid & 31, f0 = fg << 2;
    const int r0 = (tid >> 5) << 3;

    u64 acc[8][2];
#pragma unroll
    for (int i = 0; i < 8; i++) { acc[i][0] = 0ULL; acc[i][1] = 0ULL; }

#pragma unroll 8
    for (int k = 0; k < NF; k++) {
        const ulonglong2 wv = *(const ulonglong2*)&wT[widx(k, fg)];  // LDS.128
#pragma unroll
        for (int i = 0; i < 8; i++) {
            u64 aa = splat2(aN[(r0 + i) * NF + k]);   // warp-broadcast LDS + ALU splat
            fma2(acc[i][0], aa, wv.x);
            fma2(acc[i][1], aa, wv.y);
        }
    }

    float4 bv = make_float4(0.f, 0.f, 0.f, 0.f);
    if (HASB) bv = *(const float4*)(bias + f0);

#pragma unroll
    for (int i = 0; i < 8; i++) {
        int gr = rbase + r0 + i;
        if (gr < N) {
            float2 p0 = unpack2(acc[i][0]);
            float2 p1 = unpack2(acc[i][1]);
            float4 v;
            v.x = p0.x + bv.x;
            v.y = p0.y + bv.y;
            v.z = p1.x + bv.z;
            v.w = p1.y + bv.w;
            if (SSP) { v.x = ssp(v.x); v.y = ssp(v.y); v.z = ssp(v.z); v.w = ssp(v.w); }
            *(float4*)(out + (size_t)gr * NF + f0) = v;
        }
    }
}

// ---------------------------------------------------------------------------
// Fused edge kernel: cutoff + 2-layer filter MLP + gather-mul + scatter-add.
// Persistent, 2 blocks/SM (smem 111.9 KB): w2 in smem; w1 via __ldg from
// pre-transposed global (L1-resident, same float ordering as old smem read).
// Per 64-edge tile: thread = 8 edges x 4 filters; FFMA2 inner loops.
// ---------------------------------------------------------------------------
#define EDGE_SMEM_FLOATS (NF*NF + TE*NG + TE*NF + TE)
#define EDGE_SMEM_BYTES  (EDGE_SMEM_FLOATS * 4 + 2 * TE * 4)

__global__ void __launch_bounds__(256, 2)
edge_kernel(const float* __restrict__ ea, const float* __restrict__ ew,
            const float* __restrict__ b1,
            const float* __restrict__ w2, const float* __restrict__ b2,
            const float* __restrict__ h, float* __restrict__ agg, int E)
{
    extern __shared__ float sm[];
    float* w2T  = sm;                  // NF*NF  (swizzled [k][f])
    float* eaR  = w2T + NF * NF;       // TE*NG  row-major [e][k]
    float* hN   = eaR + TE * NG;       // TE*NF  row-major [e][f]
    float* sC   = hN  + TE * NF;       // TE
    int*   sSrc = (int*)(sC + TE);     // TE
    int*   sDst = sSrc + TE;           // TE

    const int tid = threadIdx.x;

    // --- w2 to smem once per (persistent) block ---
    for (int i = tid; i < NF * NF; i += 256) {
        int f = i >> 7, k = i & (NF - 1);
        w2T[widx(k, f >> 2) + (f & 3)] = w2[i];
    }

    const int fg = tid & 31, f0 = fg << 2;
    const int e0 = (tid >> 5) << 3;
    const float4 b1v = *(const float4*)(b1 + f0);
    const float4 b2v = *(const float4*)(b2 + f0);

    const int ntiles = (E + TE - 1) / TE;
    for (int tile = blockIdx.x; tile < ntiles; tile += gridDim.x) {
        const int ebase = tile * TE;
        __syncthreads();  // protect smem reuse across iterations

        // --- load edge tile ---
        if (ebase + TE <= E) {
            const float4* eag = (const float4*)(ea + (size_t)ebase * NG);
            for (int i = tid; i < (TE * NG) / 4; i += 256)
                ((float4*)eaR)[i] = eag[i];
        } else {
            int valid = (E - ebase) * NG;
            for (int i = tid; i < TE * NG; i += 256)
                eaR[i] = (i < valid) ? ea[(size_t)ebase * NG + i] : 0.f;
        }
        if (tid < TE) {
            int ge = ebase + tid;
            if (ge < E) {
                sC[tid]   = 0.5f * (cospif(ew[ge] * 0.1f) + 1.0f);
                sSrc[tid] = g_idx[ge];
                sDst[tid] = g_idx[E + ge];
            } else {
                sC[tid] = 0.f; sSrc[tid] = 0; sDst[tid] = 0;
            }
        }
        __syncthreads();

        // --- prefetch h[src] gathers (L2-resident) ---
        float4 hs[8];
#pragma unroll
        for (int i = 0; i < 8; i++)
            hs[i] = *(const float4*)(h + (size_t)sSrc[e0 + i] * NF + f0);

        // --- layer 1: [TE,50] @ w1^T -> ssp -> hN[TE,128]; w1 from global/L1 ---
        u64 acc[8][2];
#pragma unroll
        for (int i = 0; i < 8; i++) { acc[i][0] = 0ULL; acc[i][1] = 0ULL; }

#pragma unroll 10
        for (int k = 0; k < NG; k++) {
            const ulonglong2 wv = __ldg((const ulonglong2*)&g_w1T[k * NF + f0]);
#pragma unroll
            for (int i = 0; i < 8; i++) {
                u64 aa = splat2(eaR[(e0 + i) * NG + k]);   // warp-broadcast
                fma2(acc[i][0], aa, wv.x);
                fma2(acc[i][1], aa, wv.y);
            }
        }
#pragma unroll
        for (int i = 0; i < 8; i++) {
            float2 p0 = unpack2(acc[i][0]);
            float2 p1 = unpack2(acc[i][1]);
            float4 v;
            v.x = ssp(p0.x + b1v.x);
            v.y = ssp(p0.y + b1v.y);
            v.z = ssp(p1.x + b1v.z);
            v.w = ssp(p1.y + b1v.w);
            *(float4*)&hN[(e0 + i) * NF + f0] = v;  // STS.128, conflict-free
        }
        __syncthreads();

        // --- layer 2: [TE,128] @ w2^T (smem, swizzled) ---
        u64 acc2[8][2];
#pragma unroll
        for (int i = 0; i < 8; i++) { acc2[i][0] = 0ULL; acc2[i][1] = 0ULL; }

#pragma unroll 8
        for (int k = 0; k < NF; k++) {
            const ulonglong2 wv = *(const ulonglong2*)&w2T[widx(k, fg)];
#pragma unroll
            for (int i = 0; i < 8; i++) {
                u64 aa = splat2(hN[(e0 + i) * NF + k]);    // warp-broadcast
                fma2(acc2[i][0], aa, wv.x);
                fma2(acc2[i][1], aa, wv.y);
            }
        }

        // --- epilogue: W = (l2 + b2)*C, msg = h[src]*W, vector atomic scatter ---
#pragma unroll
        for (int i = 0; i < 8; i++) {
            int ge = ebase + e0 + i;
            if (ge < E) {
                float c = sC[e0 + i];
                int   d = sDst[e0 + i];
                float2 p0 = unpack2(acc2[i][0]);
                float2 p1 = unpack2(acc2[i][1]);
                float4 m;
                m.x = (p0.x + b2v.x) * c * hs[i].x;
                m.y = (p0.y + b2v.y) * c * hs[i].y;
                m.z = (p1.x + b2v.z) * c * hs[i].z;
                m.w = (p1.y + b2v.w) * c * hs[i].w;
                atomicAdd((float4*)(agg + (size_t)d * NF + f0), m);  // red.global.v4
            }
        }
    }
}

// ---------------------------------------------------------------------------
// launch
// ---------------------------------------------------------------------------
extern "C" void kernel_launch(void* const* d_in, const int* in_sizes, int n_in,
                              void* d_out, int out_size)
{
    const float* x      = (const float*)d_in[0];
    const void*  ei     = d_in[1];             // int32 or int64 — detected on device
    const float* ew     = (const float*)d_in[2];
    const float* ea     = (const float*)d_in[3];
    const float* mlp_w1 = (const float*)d_in[4];
    const float* mlp_b1 = (const float*)d_in[5];
    const float* mlp_w2 = (const float*)d_in[6];
    const float* mlp_b2 = (const float*)d_in[7];
    const float* lin1_w = (const float*)d_in[8];
    const float* lin2_w = (const float*)d_in[9];
    const float* lin2_b = (const float*)d_in[10];
    const float* lin_w  = (const float*)d_in[11];
    const float* lin_b  = (const float*)d_in[12];

    const int N = in_sizes[0] / HID;
    const int E = in_sizes[1] / 2;

    float *hbuf, *aggbuf, *tmpbuf;
    cudaGetSymbolAddress((void**)&hbuf,   g_h);
    cudaGetSymbolAddress((void**)&aggbuf, g_agg);
    cudaGetSymbolAddress((void**)&tmpbuf, g_tmp);

    const int NODE_SMEM = (NF * NF + TE * NF) * 4;   // 98304 B
    cudaFuncSetAttribute(edge_kernel, cudaFuncAttributeMaxDynamicSharedMemorySize, EDGE_SMEM_BYTES);
    cudaFuncSetAttribute(node_gemm<false, false>, cudaFuncAttributeMaxDynamicSharedMemorySize, NODE_SMEM);
    cudaFuncSetAttribute(node_gemm<true,  true >, cudaFuncAttributeMaxDynamicSharedMemorySize, NODE_SMEM);
    cudaFuncSetAttribute(node_gemm<false, true >, cudaFuncAttributeMaxDynamicSharedMemorySize, NODE_SMEM);

    int dev = 0;
    cudaGetDevice(&dev);
    int sms = 148;
    cudaDeviceGetAttribute(&sms, cudaDevAttrMultiProcessorCount, dev);

    // 0. prep: edge_index -> int32, w1 -> transposed scratch
    detect_idx_kernel<<<1, 256>>>((const unsigned int*)ei, 2 * E);
    convert_idx_kernel<<<(2 * E + 255) / 256, 256>>>(ei, 2 * E);
    transpose_w1_kernel<<<(NF * NG + 255) / 256, 256>>>(mlp_w1);

    // 1. zero agg
    {
        int n4 = (N * NF) / 4;
        zero_kernel<<<(n4 + 255) / 256, 256>>>((float4*)aggbuf, n4);
    }
    // 2. h = x @ lin1^T
    node_gemm<false, false><<<(N + TE - 1) / TE, 256, NODE_SMEM>>>(x, lin1_w, nullptr, hbuf, N);
    // 3. fused edge MLP + gather + scatter (persistent, 2 blocks/SM)
    edge_kernel<<<2 * sms, 256, EDGE_SMEM_BYTES>>>(ea, ew, mlp_b1,
                                                   mlp_w2, mlp_b2, hbuf, aggbuf, E);
    // 4. tmp = ssp(agg @ lin2^T + b2)
    node_gemm<true, true><<<(N + TE - 1) / TE, 256, NODE_SMEM>>>(aggbuf, lin2_w, lin2_b, tmpbuf, N);
    // 5. out = tmp @ lin^T + b
    node_gemm<false, true><<<(N + TE - 1) / TE, 256, NODE_SMEM>>>(tmpbuf, lin_w, lin_b, (float*)d_out, N);
}